// round 5
// baseline (speedup 1.0000x reference)
#include <cuda_runtime.h>

#define FULLMASK 0xFFFFFFFFu
#define KNN 16
#define GB 256                       // bins per axis
#define NB2 (GB * GB)
#define XLO (-6.0f)
#define BINW (12.0f / 256.0f)
#define BSCALE (256.0f / 12.0f)
#define NCAP 32768
#define RBIG 3.0e38f

// ---- global scratch (no allocation allowed) ----
__device__ __align__(16) int g_hist[NB2];
__device__ __align__(16) int g_cnt[NB2];
__device__ __align__(16) int g_binstart[NB2 + 1];
__device__ __align__(16) float2 g_sxy[NCAP];
__device__ int g_sorig[NCAP];

static __device__ __forceinline__ int bin1(float v) {
    int b = (int)((v - XLO) * BSCALE);
    return min(max(b, 0), GB - 1);
}

// ================= setup kernels =================
__global__ void zero_kernel() {
    int i = blockIdx.x * blockDim.x + threadIdx.x;
    if (i < NB2) { g_hist[i] = 0; g_cnt[i] = 0; }
}

__global__ void hist_kernel(const float* __restrict__ p, int n) {
    int i = blockIdx.x * blockDim.x + threadIdx.x;
    if (i < n) {
        float x = p[3 * i];
        float y = p[3 * i + 1];
        atomicAdd(&g_hist[(bin1(y) << 8) | bin1(x)], 1);
    }
}

// exclusive prefix over 65536 bins: 1024 threads x 64 bins each
__global__ void prefix_kernel() {
    __shared__ int wsum[32];
    const int tid = threadIdx.x;
    const int lane = tid & 31;
    const int wid = tid >> 5;
    const int4* h4 = reinterpret_cast<const int4*>(g_hist);

    int s = 0;
#pragma unroll
    for (int j = 0; j < 16; j++) {
        int4 v = h4[tid * 16 + j];
        s += v.x + v.y + v.z + v.w;
    }
    int x = s;
#pragma unroll
    for (int d = 1; d < 32; d <<= 1) {
        int y = __shfl_up_sync(FULLMASK, x, d);
        if (lane >= d) x += y;
    }
    if (lane == 31) wsum[wid] = x;
    __syncthreads();
    if (tid < 32) {
        int w = wsum[tid];
#pragma unroll
        for (int d = 1; d < 32; d <<= 1) {
            int y = __shfl_up_sync(FULLMASK, w, d);
            if (tid >= d) w += y;
        }
        wsum[tid] = w;
    }
    __syncthreads();
    int run = x - s + (wid ? wsum[wid - 1] : 0);
#pragma unroll
    for (int j = 0; j < 16; j++) {
        int4 v = h4[tid * 16 + j];
        int4 o;
        o.x = run;
        o.y = run + v.x;
        o.z = run + v.x + v.y;
        o.w = run + v.x + v.y + v.z;
        reinterpret_cast<int4*>(g_binstart)[tid * 16 + j] = o;
        run += v.x + v.y + v.z + v.w;
    }
    if (tid == 1023) g_binstart[NB2] = run;
}

__global__ void scatter_kernel(const float* __restrict__ p, int n) {
    int i = blockIdx.x * blockDim.x + threadIdx.x;
    if (i < n) {
        float x = p[3 * i];
        float y = p[3 * i + 1];
        int key = (bin1(y) << 8) | bin1(x);
        int pos = g_binstart[key] + atomicAdd(&g_cnt[key], 1);
        g_sxy[pos] = make_float2(x, y);
        g_sorig[pos] = i;
    }
}

// ================= main kernel: one thread per query =================
__global__ void __launch_bounds__(512, 1)
knn_thread_kernel(float* __restrict__ out, int n) {
    extern __shared__ float2 pxy[];

    const int tid = threadIdx.x;
    // stage full point set (sorted by grid cell) into shared memory
    for (int j = tid; j < n; j += blockDim.x) pxy[j] = g_sxy[j];
    __syncthreads();

    const int s = blockIdx.x * blockDim.x + tid;
    if (s >= n) return;

    const float2 q = pxy[s];
    const float xq = q.x;
    const float yq = q.y;

    // top-16 d^2 list, ascending, in registers
    float kn[KNN];
#pragma unroll
    for (int i = 0; i < KNN; i++) kn[i] = RBIG;
    float kn15 = RBIG;

#define TRY_INSERT(D2)                                                \
    if ((D2) < kn15) {                                                \
        float v = (D2);                                               \
        _Pragma("unroll")                                             \
        for (int i = 0; i < KNN; i++) {                               \
            float lo = fminf(kn[i], v);                               \
            v = fmaxf(kn[i], v);                                      \
            kn[i] = lo;                                               \
        }                                                             \
        kn15 = kn[KNN - 1];                                           \
    }

    // ---- prime: 17 adjacent slots (clamped), excluding self ----
    const int W = min(max(s - 8, 0), n - 17);
#pragma unroll 4
    for (int c = W; c < W + 17; c++) {
        if (c == s) continue;
        float2 v = pxy[c];
        float dx = xq - v.x;
        float dy = yq - v.y;
        float d2 = fmaf(dx, dx, dy * dy);
        TRY_INSERT(d2);
    }

    // ---- radius-pruned grid scan ----
    float rad = sqrtf(kn15);

    auto scan_row = [&](int iy) {
        int bxlo = bin1(xq - rad);
        int bxhi = bin1(xq + rad);
        int base = iy << 8;
        int lo = __ldg(&g_binstart[base + bxlo]);
        int hi = __ldg(&g_binstart[base + bxhi + 1]);
        for (int c = lo; c < hi; c++) {
            if ((unsigned)(c - W) < 17u) continue;  // already primed
            float2 v = pxy[c];
            float dx = xq - v.x;
            float dy = yq - v.y;
            float d2 = fmaf(dx, dx, dy * dy);
            TRY_INSERT(d2);
        }
        rad = sqrtf(kn15);
    };

    const int iyq = bin1(yq);
    scan_row(iyq);
    for (int t = 1;; t++) {
        bool any = false;
        int ru = iyq + t;
        if (ru < GB && yq + rad > XLO + (float)ru * BINW) {
            scan_row(ru);
            any = true;
        }
        int rd = iyq - t;
        if (rd >= 0 && yq - rad < XLO + (float)(rd + 1) * BINW) {
            scan_row(rd);
            any = true;
        }
        if (!any) break;
    }
#undef TRY_INSERT

    // ---- output: sorted distances, scattered to original row ----
    const int orig = __ldg(&g_sorig[s]);
    float4* o = reinterpret_cast<float4*>(out + (size_t)orig * KNN);
    float4 r0, r1, r2, r3;
    r0.x = sqrtf(kn[0]);  r0.y = sqrtf(kn[1]);  r0.z = sqrtf(kn[2]);  r0.w = sqrtf(kn[3]);
    r1.x = sqrtf(kn[4]);  r1.y = sqrtf(kn[5]);  r1.z = sqrtf(kn[6]);  r1.w = sqrtf(kn[7]);
    r2.x = sqrtf(kn[8]);  r2.y = sqrtf(kn[9]);  r2.z = sqrtf(kn[10]); r2.w = sqrtf(kn[11]);
    r3.x = sqrtf(kn[12]); r3.y = sqrtf(kn[13]); r3.z = sqrtf(kn[14]); r3.w = sqrtf(kn[15]);
    o[0] = r0; o[1] = r1; o[2] = r2; o[3] = r3;
}

extern "C" void kernel_launch(void* const* d_in, const int* in_sizes, int n_in,
                              void* d_out, int out_size) {
    const float* p = (const float*)d_in[0];
    float* out = (float*)d_out;
    int n = in_sizes[0] / 3;

    int nb = (n + 1023) / 1024;
    zero_kernel<<<(NB2 + 1023) / 1024, 1024>>>();
    hist_kernel<<<nb, 1024>>>(p, n);
    prefix_kernel<<<1, 1024>>>();
    scatter_kernel<<<nb, 1024>>>(p, n);

    size_t smem = (size_t)n * sizeof(float2);
    cudaFuncSetAttribute(knn_thread_kernel,
                         cudaFuncAttributeMaxDynamicSharedMemorySize, (int)smem);
    int blocks = (n + 511) / 512;
    knn_thread_kernel<<<blocks, 512, smem>>>(out, n);
}

// round 6
// speedup vs baseline: 1.0158x; 1.0158x over previous
#include <cuda_runtime.h>

#define FULLMASK 0xFFFFFFFFu
#define KNN 16
#define GB 256                       // bins per axis
#define NB2 (GB * GB)
#define XLO (-6.0f)
#define BINW (12.0f / 256.0f)
#define BSCALE (256.0f / 12.0f)
#define NCAP 32768
#define RBIG 3.0e38f

// ---- global scratch (no allocation allowed) ----
__device__ __align__(16) int g_hist[NB2];
__device__ __align__(16) int g_cnt[NB2];
__device__ __align__(16) int g_binstart[NB2 + 1];
__device__ __align__(16) float2 g_sxy[NCAP];
__device__ int g_sorig[NCAP];

static __device__ __forceinline__ int bin1(float v) {
    int b = (int)((v - XLO) * BSCALE);
    return min(max(b, 0), GB - 1);
}

// ================= setup kernels =================
__global__ void zero_kernel() {
    int i = blockIdx.x * blockDim.x + threadIdx.x;
    if (i < NB2) { g_hist[i] = 0; g_cnt[i] = 0; }
}

__global__ void hist_kernel(const float* __restrict__ p, int n) {
    int i = blockIdx.x * blockDim.x + threadIdx.x;
    if (i < n) {
        float x = p[3 * i];
        float y = p[3 * i + 1];
        atomicAdd(&g_hist[(bin1(y) << 8) | bin1(x)], 1);
    }
}

// exclusive prefix over 65536 bins: 1024 threads x 64 bins each
__global__ void prefix_kernel() {
    __shared__ int wsum[32];
    const int tid = threadIdx.x;
    const int lane = tid & 31;
    const int wid = tid >> 5;
    const int4* h4 = reinterpret_cast<const int4*>(g_hist);

    int s = 0;
#pragma unroll
    for (int j = 0; j < 16; j++) {
        int4 v = h4[tid * 16 + j];
        s += v.x + v.y + v.z + v.w;
    }
    int x = s;
#pragma unroll
    for (int d = 1; d < 32; d <<= 1) {
        int y = __shfl_up_sync(FULLMASK, x, d);
        if (lane >= d) x += y;
    }
    if (lane == 31) wsum[wid] = x;
    __syncthreads();
    if (tid < 32) {
        int w = wsum[tid];
#pragma unroll
        for (int d = 1; d < 32; d <<= 1) {
            int y = __shfl_up_sync(FULLMASK, w, d);
            if (tid >= d) w += y;
        }
        wsum[tid] = w;
    }
    __syncthreads();
    int run = x - s + (wid ? wsum[wid - 1] : 0);
#pragma unroll
    for (int j = 0; j < 16; j++) {
        int4 v = h4[tid * 16 + j];
        int4 o;
        o.x = run;
        o.y = run + v.x;
        o.z = run + v.x + v.y;
        o.w = run + v.x + v.y + v.z;
        reinterpret_cast<int4*>(g_binstart)[tid * 16 + j] = o;
        run += v.x + v.y + v.z + v.w;
    }
    if (tid == 1023) g_binstart[NB2] = run;
}

__global__ void scatter_kernel(const float* __restrict__ p, int n) {
    int i = blockIdx.x * blockDim.x + threadIdx.x;
    if (i < n) {
        float x = p[3 * i];
        float y = p[3 * i + 1];
        int key = (bin1(y) << 8) | bin1(x);
        int pos = g_binstart[key] + atomicAdd(&g_cnt[key], 1);
        g_sxy[pos] = make_float2(x, y);
        g_sorig[pos] = i;
    }
}

// ================= main kernel: one thread per query, L1-resident points ====
__global__ void __launch_bounds__(128, 1)
knn_thread_kernel(float* __restrict__ out, int n) {
    const int s = blockIdx.x * blockDim.x + threadIdx.x;
    if (s >= n) return;

    const float2 q = __ldg(&g_sxy[s]);
    const float xq = q.x;
    const float yq = q.y;

    // top-16 d^2 list, ascending, in registers
    float kn[KNN];
#pragma unroll
    for (int i = 0; i < KNN; i++) kn[i] = RBIG;
    float kn15 = RBIG;

#define TRY_INSERT(D2)                                                \
    if ((D2) < kn15) {                                                \
        float v = (D2);                                               \
        _Pragma("unroll")                                             \
        for (int i = 0; i < KNN; i++) {                               \
            float lo = fminf(kn[i], v);                               \
            v = fmaxf(kn[i], v);                                      \
            kn[i] = lo;                                               \
        }                                                             \
        kn15 = kn[KNN - 1];                                           \
    }

    // ---- prime: 17 adjacent slots (clamped), excluding self ----
    const int W = min(max(s - 8, 0), n - 17);
#pragma unroll 4
    for (int c = W; c < W + 17; c++) {
        if (c == s) continue;
        float2 v = __ldg(&g_sxy[c]);
        float dx = xq - v.x;
        float dy = yq - v.y;
        float d2 = fmaf(dx, dx, dy * dy);
        TRY_INSERT(d2);
    }

    // ---- radius-pruned grid scan ----
    float rad = sqrtf(kn15);

    auto scan_row = [&](int iy) {
        int bxlo = bin1(xq - rad);
        int bxhi = bin1(xq + rad);
        int base = iy << 8;
        int lo = __ldg(&g_binstart[base + bxlo]);
        int hi = __ldg(&g_binstart[base + bxhi + 1]);
        for (int c = lo; c < hi; c++) {
            if ((unsigned)(c - W) < 17u) continue;  // already primed
            float2 v = __ldg(&g_sxy[c]);
            float dx = xq - v.x;
            float dy = yq - v.y;
            float d2 = fmaf(dx, dx, dy * dy);
            TRY_INSERT(d2);
        }
        rad = sqrtf(kn15);
    };

    const int iyq = bin1(yq);
    scan_row(iyq);
    for (int t = 1;; t++) {
        bool any = false;
        int ru = iyq + t;
        if (ru < GB && yq + rad > XLO + (float)ru * BINW) {
            scan_row(ru);
            any = true;
        }
        int rd = iyq - t;
        if (rd >= 0 && yq - rad < XLO + (float)(rd + 1) * BINW) {
            scan_row(rd);
            any = true;
        }
        if (!any) break;
    }
#undef TRY_INSERT

    // ---- output: sorted distances, scattered to original row ----
    const int orig = __ldg(&g_sorig[s]);
    float4* o = reinterpret_cast<float4*>(out + (size_t)orig * KNN);
    float4 r0, r1, r2, r3;
    r0.x = sqrtf(kn[0]);  r0.y = sqrtf(kn[1]);  r0.z = sqrtf(kn[2]);  r0.w = sqrtf(kn[3]);
    r1.x = sqrtf(kn[4]);  r1.y = sqrtf(kn[5]);  r1.z = sqrtf(kn[6]);  r1.w = sqrtf(kn[7]);
    r2.x = sqrtf(kn[8]);  r2.y = sqrtf(kn[9]);  r2.z = sqrtf(kn[10]); r2.w = sqrtf(kn[11]);
    r3.x = sqrtf(kn[12]); r3.y = sqrtf(kn[13]); r3.z = sqrtf(kn[14]); r3.w = sqrtf(kn[15]);
    o[0] = r0; o[1] = r1; o[2] = r2; o[3] = r3;
}

extern "C" void kernel_launch(void* const* d_in, const int* in_sizes, int n_in,
                              void* d_out, int out_size) {
    const float* p = (const float*)d_in[0];
    float* out = (float*)d_out;
    int n = in_sizes[0] / 3;

    int nb = (n + 1023) / 1024;
    zero_kernel<<<(NB2 + 1023) / 1024, 1024>>>();
    hist_kernel<<<nb, 1024>>>(p, n);
    prefix_kernel<<<1, 1024>>>();
    scatter_kernel<<<nb, 1024>>>(p, n);

    int blocks = (n + 127) / 128;
    knn_thread_kernel<<<blocks, 128>>>(out, n);
}